// round 1
// baseline (speedup 1.0000x reference)
#include <cuda_runtime.h>
#include <cuda_bf16.h>

#define BB 2
#define NN 16384
#define PP 4096
#define CC 64
#define SS 32
#define CH (3 + CC)   // 67

// Scratch (no cudaMalloc allowed)
__device__ float4 g_xyz4[BB * NN];          // padded xyz, 512 KB
__device__ float  g_ftrt[BB * NN * CC];     // features transposed to (B,N,C), 8.4 MB
__device__ int    g_idx [BB * PP * SS];     // ball query result, 1 MB

// ---------------------------------------------------------------------------
// Pack xyz (B,N,3) -> float4 (B,N) for single-LDG.128 access in the scan.
// ---------------------------------------------------------------------------
__global__ void pack_xyz_kernel(const float* __restrict__ xyz) {
    int i = blockIdx.x * blockDim.x + threadIdx.x;
    if (i < BB * NN) {
        g_xyz4[i] = make_float4(xyz[3 * i + 0], xyz[3 * i + 1], xyz[3 * i + 2], 0.0f);
    }
}

// ---------------------------------------------------------------------------
// Transpose features (B,C,N) -> (B,N,C) so per-point channel gathers are
// contiguous (256 B per point, full sectors).
// ---------------------------------------------------------------------------
__global__ void transpose_feat_kernel(const float* __restrict__ f) {
    __shared__ float tile[32][33];
    int b  = blockIdx.z;
    int n0 = blockIdx.x * 32;
    int c0 = blockIdx.y * 32;
    int tx = threadIdx.x, ty = threadIdx.y;   // block (32,8)
#pragma unroll
    for (int j = 0; j < 32; j += 8)
        tile[ty + j][tx] = f[((size_t)b * CC + (c0 + ty + j)) * NN + n0 + tx];
    __syncthreads();
#pragma unroll
    for (int j = 0; j < 32; j += 8)
        g_ftrt[((size_t)b * NN + (n0 + ty + j)) * CC + c0 + tx] = tile[tx][ty + j];
}

// ---------------------------------------------------------------------------
// Ball query: one warp per query point. Lanes scan 32 consecutive point
// indices per iteration; ballot gives in-index-order ranks (PointNet++
// semantics: first `nsample` hits in index order, pad with first hit / 0).
// Threshold: jax compares f32 d2 < f32(0.01) -> 0.01f literal.
// ---------------------------------------------------------------------------
__global__ void ball_query_kernel(const float* __restrict__ new_xyz) {
    int w    = (blockIdx.x * blockDim.x + threadIdx.x) >> 5;   // query id
    int lane = threadIdx.x & 31;
    if (w >= BB * PP) return;
    int b = w / PP;

    float qx = new_xyz[3 * w + 0];
    float qy = new_xyz[3 * w + 1];
    float qz = new_xyz[3 * w + 2];

    const float4* __restrict__ pts = g_xyz4 + (size_t)b * NN;
    int* __restrict__ out = g_idx + (size_t)w * SS;

    int cnt = 0;
    int first = -1;
    for (int base = 0; base < NN && cnt < SS; base += 32) {
        float4 pt = pts[base + lane];
        float dx = qx - pt.x;
        float dy = qy - pt.y;
        float dz = qz - pt.z;
        float d2 = __fmaf_rn(dz, dz, __fmaf_rn(dy, dy, __fmul_rn(dx, dx)));
        unsigned m = __ballot_sync(0xffffffffu, d2 < 0.01f);
        if (m) {
            if (first < 0) first = base + __ffs(m) - 1;
            int rank = cnt + __popc(m & ((1u << lane) - 1u));
            if (((m >> lane) & 1u) && rank < SS) out[rank] = base + lane;
            cnt += __popc(m);
        }
    }
    if (first < 0) first = 0;
    if (lane >= cnt) out[lane] = first;     // pad remaining slots
}

// ---------------------------------------------------------------------------
// Grouping: one warp per query, lane = sample slot s.
// Lane gathers its point's 64 channels contiguously from the transposed
// features (registers only), then per-channel writes are coalesced 128 B.
// ---------------------------------------------------------------------------
__global__ void group_kernel(const float* __restrict__ new_xyz,
                             float* __restrict__ out) {
    int w    = (blockIdx.x * blockDim.x + threadIdx.x) >> 5;
    int lane = threadIdx.x & 31;
    if (w >= BB * PP) return;
    int b = w / PP;
    int p = w % PP;

    int i = g_idx[(size_t)w * SS + lane];

    float qx = new_xyz[3 * w + 0];
    float qy = new_xyz[3 * w + 1];
    float qz = new_xyz[3 * w + 2];

    float4 pt = g_xyz4[(size_t)b * NN + i];

    const size_t chStride = (size_t)PP * SS;                       // 131072
    size_t obase = (((size_t)b * CH) * PP + p) * SS + lane;        // ch = 0

    out[obase + 0 * chStride] = pt.x - qx;
    out[obase + 1 * chStride] = pt.y - qy;
    out[obase + 2 * chStride] = pt.z - qz;

    // Gather 64 contiguous channel values for this lane's point
    const float4* __restrict__ f4 =
        (const float4*)(g_ftrt + ((size_t)b * NN + i) * CC);
    float4 v[16];
#pragma unroll
    for (int j = 0; j < 16; j++) v[j] = f4[j];

    size_t fo = obase + 3 * chStride;
#pragma unroll
    for (int j = 0; j < 16; j++) {
        out[fo + (size_t)(4 * j + 0) * chStride] = v[j].x;
        out[fo + (size_t)(4 * j + 1) * chStride] = v[j].y;
        out[fo + (size_t)(4 * j + 2) * chStride] = v[j].z;
        out[fo + (size_t)(4 * j + 3) * chStride] = v[j].w;
    }
}

// ---------------------------------------------------------------------------
extern "C" void kernel_launch(void* const* d_in, const int* in_sizes, int n_in,
                              void* d_out, int out_size) {
    const float* xyz     = (const float*)d_in[0];   // (2,16384,3)
    const float* new_xyz = (const float*)d_in[1];   // (2,4096,3)
    const float* feat    = (const float*)d_in[2];   // (2,64,16384)
    float* out = (float*)d_out;                     // (2,67,4096,32)

    pack_xyz_kernel<<<(BB * NN + 255) / 256, 256>>>(xyz);

    dim3 tb(32, 8), tg(NN / 32, CC / 32, BB);
    transpose_feat_kernel<<<tg, tb>>>(feat);

    // one warp per query: B*P warps, 8 warps per 256-thread block
    ball_query_kernel<<<(BB * PP) / 8, 256>>>(new_xyz);

    group_kernel<<<(BB * PP) / 8, 256>>>(new_xyz, out);
}

// round 2
// speedup vs baseline: 3.5086x; 3.5086x over previous
#include <cuda_runtime.h>
#include <cuda_bf16.h>

#define BB 2
#define NN 16384
#define PP 4096
#define CC 64
#define SS 32
#define CH (3 + CC)   // 67
#define GC 10         // grid cells per dim
#define NCELL (GC*GC*GC)
#define HB 320        // per-warp hit buffer capacity

// ---- scratch (__device__ globals; no cudaMalloc allowed) ----
__device__ float4 g_xyz4[BB * NN];           // packed xyz (idx-order)
__device__ float  g_ftrt[BB * NN * CC];      // features transposed to (B,N,C)
__device__ int    g_idx [BB * PP * SS];      // ball query result
__device__ float4 g_pts [BB * NN];           // cell-sorted points, .w = __int_as_float(idx)
__device__ int    g_cnt [BB * NCELL];        // per-cell counts
__device__ int    g_cur [BB * NCELL];        // scatter cursors
__device__ int    g_start[BB * (NCELL + 1)]; // exclusive scan (+ total)

__device__ __forceinline__ int cell_of(float x, float y, float z) {
    int cx = min((int)(x * 10.0f), GC - 1);
    int cy = min((int)(y * 10.0f), GC - 1);
    int cz = min((int)(z * 10.0f), GC - 1);
    return (cz * GC + cy) * GC + cx;
}

// ---------------------------------------------------------------------------
__global__ void zero_counts_kernel() {
    int i = blockIdx.x * blockDim.x + threadIdx.x;
    if (i < BB * NCELL) { g_cnt[i] = 0; g_cur[i] = 0; }
}

// pack xyz -> float4 AND histogram cells
__global__ void pack_count_kernel(const float* __restrict__ xyz) {
    int i = blockIdx.x * blockDim.x + threadIdx.x;
    if (i >= BB * NN) return;
    float x = xyz[3 * i + 0], y = xyz[3 * i + 1], z = xyz[3 * i + 2];
    g_xyz4[i] = make_float4(x, y, z, 0.0f);
    int b = i / NN;
    atomicAdd(&g_cnt[b * NCELL + cell_of(x, y, z)], 1);
}

// single-block exclusive scan of the 1000 counts per batch
__global__ void scan_kernel() {
    __shared__ int s[1024];
    int t = threadIdx.x;
    for (int b = 0; b < BB; b++) {
        int v = (t < NCELL) ? g_cnt[b * NCELL + t] : 0;
        s[t] = v; __syncthreads();
        for (int off = 1; off < 1024; off <<= 1) {
            int u = (t >= off) ? s[t - off] : 0;
            __syncthreads();
            s[t] += u;
            __syncthreads();
        }
        if (t < NCELL) g_start[b * (NCELL + 1) + t + 1] = s[t];
        if (t == 0)    g_start[b * (NCELL + 1)] = 0;
        __syncthreads();
    }
}

// scatter points into cell-sorted order (order within cell irrelevant:
// final selection sorts hits by original index)
__global__ void scatter_kernel(const float* __restrict__ xyz) {
    int i = blockIdx.x * blockDim.x + threadIdx.x;
    if (i >= BB * NN) return;
    float x = xyz[3 * i + 0], y = xyz[3 * i + 1], z = xyz[3 * i + 2];
    int b = i / NN, n = i % NN;
    int c = cell_of(x, y, z);
    int pos = g_start[b * (NCELL + 1) + c] + atomicAdd(&g_cur[b * NCELL + c], 1);
    g_pts[b * NN + pos] = make_float4(x, y, z, __int_as_float(n));
}

// ---------------------------------------------------------------------------
// transpose features (B,C,N) -> (B,N,C)
// ---------------------------------------------------------------------------
__global__ void transpose_feat_kernel(const float* __restrict__ f) {
    __shared__ float tile[32][33];
    int b  = blockIdx.z;
    int n0 = blockIdx.x * 32;
    int c0 = blockIdx.y * 32;
    int tx = threadIdx.x, ty = threadIdx.y;   // (32,8)
#pragma unroll
    for (int j = 0; j < 32; j += 8)
        tile[ty + j][tx] = f[((size_t)b * CC + (c0 + ty + j)) * NN + n0 + tx];
    __syncthreads();
#pragma unroll
    for (int j = 0; j < 32; j += 8)
        g_ftrt[((size_t)b * NN + (n0 + ty + j)) * CC + c0 + tx] = tile[tx][ty + j];
}

// ---------------------------------------------------------------------------
// Grid ball query: one warp per query. Scan 9 contiguous cell ranges
// (27 cells), collect ALL hits, then rank by original index to reproduce
// PointNet++ first-nsample-in-index-order + pad-with-first semantics.
// Threshold 0.01f and fma chain frozen (bit-exact vs reference in R1).
// ---------------------------------------------------------------------------
__global__ void ball_query_grid_kernel(const float* __restrict__ new_xyz) {
    __shared__ int hb[8][HB];
    int w    = (blockIdx.x * blockDim.x + threadIdx.x) >> 5;
    int lane = threadIdx.x & 31;
    if (w >= BB * PP) return;
    int b = w / PP;
    int* buf = hb[(threadIdx.x >> 5) & 7];

    float qx = new_xyz[3 * w + 0];
    float qy = new_xyz[3 * w + 1];
    float qz = new_xyz[3 * w + 2];
    int cx = min((int)(qx * 10.0f), GC - 1);
    int cy = min((int)(qy * 10.0f), GC - 1);
    int cz = min((int)(qz * 10.0f), GC - 1);
    int x0 = max(cx - 1, 0), x1 = min(cx + 1, GC - 1);

    const int*    st  = g_start + b * (NCELL + 1);
    const float4* pts = g_pts + (size_t)b * NN;

    int K = 0;
    for (int dz = -1; dz <= 1; dz++) {
        int z = cz + dz;
        if (z < 0 || z >= GC) continue;
        for (int dy = -1; dy <= 1; dy++) {
            int y = cy + dy;
            if (y < 0 || y >= GC) continue;
            int row = (z * GC + y) * GC;
            int rs = st[row + x0];
            int re = st[row + x1 + 1];
            for (int base = rs; base < re; base += 32) {
                int j = base + lane;
                bool hit = false; int id = 0;
                if (j < re) {
                    float4 p = pts[j];
                    float dx = qx - p.x, dy2 = qy - p.y, dz2 = qz - p.z;
                    float d2 = __fmaf_rn(dz2, dz2,
                               __fmaf_rn(dy2, dy2, __fmul_rn(dx, dx)));
                    hit = d2 < 0.01f;
                    id  = __float_as_int(p.w);
                }
                unsigned m = __ballot_sync(0xffffffffu, hit);
                if (hit) {
                    int pos = K + __popc(m & ((1u << lane) - 1u));
                    if (pos < HB) buf[pos] = id;
                }
                K += __popc(m);
            }
        }
    }
    if (K > HB) K = HB;
    __syncwarp();

    int* out = g_idx + (size_t)w * SS;
    int cnt  = min(K, SS);
    int padv = 0x7fffffff;
    int G = (K + 31) >> 5;
    for (int g = 0; g < G; g++) {
        int t = g * 32 + lane;
        bool val = t < K;
        int v = val ? buf[t] : 0x7fffffff;
        int r = 0;
        for (int u = 0; u < K; u++)          // broadcast LDS, conflict-free
            r += (buf[u] < v);
        if (val && r < SS) out[r] = v;
        padv = min(padv, v);
    }
#pragma unroll
    for (int o = 16; o; o >>= 1)
        padv = min(padv, __shfl_xor_sync(0xffffffffu, padv, o));
    if (K == 0) padv = 0;
    if (lane >= cnt) out[lane] = padv;       // pad with first (= min index)
}

// ---------------------------------------------------------------------------
// Grouping: one warp per query. Feature gather staged through shared:
// 16 lanes cover one point's contiguous 256B row -> each LDG.128 touches
// only 4 lines (2 points) instead of 32. Pad 65 -> conflict-free LDS.
// ---------------------------------------------------------------------------
__global__ void __launch_bounds__(128) group_kernel(
        const float* __restrict__ new_xyz, float* __restrict__ out) {
    __shared__ float stage[4][32][65];
    int w    = (blockIdx.x * blockDim.x + threadIdx.x) >> 5;
    int lane = threadIdx.x & 31;
    if (w >= BB * PP) return;
    int b = w / PP;
    int p = w % PP;
    float (*st)[65] = stage[(threadIdx.x >> 5) & 3];

    int i = g_idx[(size_t)w * SS + lane];

    float qx = new_xyz[3 * w + 0];
    float qy = new_xyz[3 * w + 1];
    float qz = new_xyz[3 * w + 2];

    float4 pt = g_xyz4[(size_t)b * NN + i];

    const size_t chStride = (size_t)PP * SS;
    size_t obase = (((size_t)b * CH) * PP + p) * SS + lane;

    out[obase + 0 * chStride] = pt.x - qx;
    out[obase + 1 * chStride] = pt.y - qy;
    out[obase + 2 * chStride] = pt.z - qz;

    // gather 32 points x 64ch, 2 points per LDG.128
    int half = lane >> 4;          // 0: point 2j, 1: point 2j+1
    int c    = lane & 15;          // 16B chunk within point row
#pragma unroll
    for (int j = 0; j < 16; j++) {
        int ptid = 2 * j + half;
        int ii = __shfl_sync(0xffffffffu, i, ptid);
        const float4* src =
            (const float4*)(g_ftrt + ((size_t)b * NN + ii) * CC) + c;
        float4 v = *src;
        float* d = &st[ptid][c * 4];
        d[0] = v.x; d[1] = v.y; d[2] = v.z; d[3] = v.w;
    }
    __syncwarp();

    size_t fo = obase + 3 * chStride;
#pragma unroll
    for (int ch = 0; ch < CC; ch++)
        out[fo + (size_t)ch * chStride] = st[lane][ch];
}

// ---------------------------------------------------------------------------
extern "C" void kernel_launch(void* const* d_in, const int* in_sizes, int n_in,
                              void* d_out, int out_size) {
    const float* xyz     = (const float*)d_in[0];   // (2,16384,3)
    const float* new_xyz = (const float*)d_in[1];   // (2,4096,3)
    const float* feat    = (const float*)d_in[2];   // (2,64,16384)
    float* out = (float*)d_out;                     // (2,67,4096,32)

    zero_counts_kernel<<<(BB * NCELL + 255) / 256, 256>>>();
    pack_count_kernel<<<(BB * NN + 255) / 256, 256>>>(xyz);
    scan_kernel<<<1, 1024>>>();
    scatter_kernel<<<(BB * NN + 255) / 256, 256>>>(xyz);

    dim3 tb(32, 8), tg(NN / 32, CC / 32, BB);
    transpose_feat_kernel<<<tg, tb>>>(feat);

    ball_query_grid_kernel<<<(BB * PP) / 8, 256>>>(new_xyz);

    group_kernel<<<(BB * PP) / 4, 128>>>(new_xyz, out);
}